// round 1
// baseline (speedup 1.0000x reference)
#include <cuda_runtime.h>

// EdgeBlock: cell scatter-sum + fused 2-layer edge MLP.
// Stage 1: cell_attr[c][:] = sum_{j<3} node_attr[cells_node[3c+j]][:]
// Stage 2: out[e] = relu([cell_attr[s], cell_attr[r]*mask, edge_attr[e]] @ W1 + b1) @ W2 + b2
//
// fp32 baseline using packed fma.rn.f32x2 (FFMA2) for 2x fp32 density.

#define DIMF 128
#define TILE_E 64
#define NTHREADS 256

// row strides (floats) in shared memory
#define COLL_STRIDE 388   // 384 + 4 pad
#define H_STRIDE    132   // 128 + 4 pad

// scratch for cell_attr: C = 400,000 cells x 128 floats (204.8 MB)
__device__ float g_cell_attr[400000 * 128];

// ---------------- packed f32x2 helpers ----------------
__device__ __forceinline__ unsigned long long pack_dup(float a) {
    unsigned long long r;
    asm("mov.b64 %0, {%1, %1};" : "=l"(r) : "f"(a));
    return r;
}
__device__ __forceinline__ unsigned long long pack2(float a, float b) {
    unsigned long long r;
    asm("mov.b64 %0, {%1, %2};" : "=l"(r) : "f"(a), "f"(b));
    return r;
}
__device__ __forceinline__ void ffma2(unsigned long long& d,
                                      unsigned long long a,
                                      unsigned long long b) {
    asm("fma.rn.f32x2 %0, %1, %2, %0;" : "+l"(d) : "l"(a), "l"(b));
}
__device__ __forceinline__ float2 unpack2(unsigned long long v) {
    float2 f;
    asm("mov.b64 {%0, %1}, %2;" : "=f"(f.x), "=f"(f.y) : "l"(v));
    return f;
}

// ---------------- stage 1: cell scatter-sum ----------------
__global__ void cell_sum_kernel(const float* __restrict__ node_attr,
                                const int* __restrict__ cells_node,
                                float* __restrict__ cell_attr,
                                int C) {
    int warp = (blockIdx.x * blockDim.x + threadIdx.x) >> 5;
    int lane = threadIdx.x & 31;
    if (warp >= C) return;
    int n0 = cells_node[3 * warp + 0];
    int n1 = cells_node[3 * warp + 1];
    int n2 = cells_node[3 * warp + 2];
    float4 a = ((const float4*)(node_attr + (size_t)n0 * DIMF))[lane];
    float4 b = ((const float4*)(node_attr + (size_t)n1 * DIMF))[lane];
    float4 c = ((const float4*)(node_attr + (size_t)n2 * DIMF))[lane];
    float4 s;
    s.x = a.x + b.x + c.x;
    s.y = a.y + b.y + c.y;
    s.z = a.z + b.z + c.z;
    s.w = a.w + b.w + c.w;
    ((float4*)(cell_attr + (size_t)warp * DIMF))[lane] = s;
}

// ---------------- stage 2: fused edge MLP ----------------
// Block = 256 threads, processes TILE_E=64 edges, full 128 output cols.
// Thread grid 16x16: ty -> 4 edges, tx -> 8 cols (4 col-pairs as f32x2).
__global__ __launch_bounds__(NTHREADS, 1)
void edge_mlp_kernel(const float* __restrict__ cell_attr,
                     const float* __restrict__ edge_attr,
                     const float* __restrict__ W1,
                     const float* __restrict__ b1,
                     const float* __restrict__ W2,
                     const float* __restrict__ b2,
                     const int* __restrict__ edge_index,
                     float* __restrict__ out,
                     int E) {
    extern __shared__ float smem[];
    float* sColl = smem;                        // [64][COLL_STRIDE]
    float* sW    = sColl + TILE_E * COLL_STRIDE; // [64][128] weight chunk
    float* sH    = sW + 64 * 128;                // [64][H_STRIDE]

    const int tid = threadIdx.x;
    const int eb  = blockIdx.x * TILE_E;

    // ---- fill collected[64][384] : [cell_attr[s] | cell_attr[r]*mask | edge_attr] ----
    {
        int w = tid >> 5, lane = tid & 31;
        #pragma unroll
        for (int i = w; i < TILE_E; i += 8) {
            int e = eb + i;
            if (e < E) {
                int s = edge_index[e];
                int r = edge_index[E + e];
                float m = (s != r) ? 1.0f : 0.0f;
                float4 sa = ((const float4*)(cell_attr + (size_t)s * DIMF))[lane];
                float4 ra = ((const float4*)(cell_attr + (size_t)r * DIMF))[lane];
                float4 ea = ((const float4*)(edge_attr + (size_t)e * DIMF))[lane];
                ra.x *= m; ra.y *= m; ra.z *= m; ra.w *= m;
                *(float4*)&sColl[i * COLL_STRIDE +   0 + lane * 4] = sa;
                *(float4*)&sColl[i * COLL_STRIDE + 128 + lane * 4] = ra;
                *(float4*)&sColl[i * COLL_STRIDE + 256 + lane * 4] = ea;
            }
        }
    }

    const int tx = tid & 15;   // col group: cols cx..cx+7
    const int ty = tid >> 4;   // edge group: edges ey..ey+3
    const int cx = tx * 8;
    const int ey = ty * 4;

    unsigned long long acc[4][4];

    // init acc with b1
    {
        float4 bb0 = *(const float4*)&b1[cx];
        float4 bb1 = *(const float4*)&b1[cx + 4];
        unsigned long long pb[4];
        pb[0] = pack2(bb0.x, bb0.y);
        pb[1] = pack2(bb0.z, bb0.w);
        pb[2] = pack2(bb1.x, bb1.y);
        pb[3] = pack2(bb1.z, bb1.w);
        #pragma unroll
        for (int i = 0; i < 4; i++)
            #pragma unroll
            for (int j = 0; j < 4; j++)
                acc[i][j] = pb[j];
    }

    // ---- layer 1: [64,384] @ [384,128], W1 staged in 64-row chunks ----
    for (int kk = 0; kk < 384; kk += 64) {
        __syncthreads();   // protect sColl fill (first iter) / sW reuse
        // stage W1[kk..kk+63][0..127]
        {
            const float4* src = (const float4*)(W1 + (size_t)kk * DIMF);
            float4* dst = (float4*)sW;
            #pragma unroll
            for (int idx = tid; idx < 64 * 128 / 4; idx += NTHREADS)
                dst[idx] = src[idx];
        }
        __syncthreads();

        const float* a0p = sColl + (ey + 0) * COLL_STRIDE + kk;
        const float* a1p = sColl + (ey + 1) * COLL_STRIDE + kk;
        const float* a2p = sColl + (ey + 2) * COLL_STRIDE + kk;
        const float* a3p = sColl + (ey + 3) * COLL_STRIDE + kk;

        #pragma unroll 8
        for (int k = 0; k < 64; k++) {
            unsigned long long pa0 = pack_dup(a0p[k]);
            unsigned long long pa1 = pack_dup(a1p[k]);
            unsigned long long pa2 = pack_dup(a2p[k]);
            unsigned long long pa3 = pack_dup(a3p[k]);
            ulonglong2 w01 = *(const ulonglong2*)&sW[k * 128 + cx];
            ulonglong2 w23 = *(const ulonglong2*)&sW[k * 128 + cx + 4];
            ffma2(acc[0][0], pa0, w01.x); ffma2(acc[0][1], pa0, w01.y);
            ffma2(acc[0][2], pa0, w23.x); ffma2(acc[0][3], pa0, w23.y);
            ffma2(acc[1][0], pa1, w01.x); ffma2(acc[1][1], pa1, w01.y);
            ffma2(acc[1][2], pa1, w23.x); ffma2(acc[1][3], pa1, w23.y);
            ffma2(acc[2][0], pa2, w01.x); ffma2(acc[2][1], pa2, w01.y);
            ffma2(acc[2][2], pa2, w23.x); ffma2(acc[2][3], pa2, w23.y);
            ffma2(acc[3][0], pa3, w01.x); ffma2(acc[3][1], pa3, w01.y);
            ffma2(acc[3][2], pa3, w23.x); ffma2(acc[3][3], pa3, w23.y);
        }
    }

    // ---- relu + write h to sH ----
    #pragma unroll
    for (int i = 0; i < 4; i++) {
        float2 v0 = unpack2(acc[i][0]);
        float2 v1 = unpack2(acc[i][1]);
        float2 v2 = unpack2(acc[i][2]);
        float2 v3 = unpack2(acc[i][3]);
        float4 h0, h1;
        h0.x = fmaxf(v0.x, 0.f); h0.y = fmaxf(v0.y, 0.f);
        h0.z = fmaxf(v1.x, 0.f); h0.w = fmaxf(v1.y, 0.f);
        h1.x = fmaxf(v2.x, 0.f); h1.y = fmaxf(v2.y, 0.f);
        h1.z = fmaxf(v3.x, 0.f); h1.w = fmaxf(v3.y, 0.f);
        *(float4*)&sH[(ey + i) * H_STRIDE + cx]     = h0;
        *(float4*)&sH[(ey + i) * H_STRIDE + cx + 4] = h1;
    }

    // re-init acc with b2
    {
        float4 bb0 = *(const float4*)&b2[cx];
        float4 bb1 = *(const float4*)&b2[cx + 4];
        unsigned long long pb[4];
        pb[0] = pack2(bb0.x, bb0.y);
        pb[1] = pack2(bb0.z, bb0.w);
        pb[2] = pack2(bb1.x, bb1.y);
        pb[3] = pack2(bb1.z, bb1.w);
        #pragma unroll
        for (int i = 0; i < 4; i++)
            #pragma unroll
            for (int j = 0; j < 4; j++)
                acc[i][j] = pb[j];
    }

    // ---- layer 2: [64,128] @ [128,128], W2 staged in 64-row chunks ----
    for (int kk = 0; kk < 128; kk += 64) {
        __syncthreads();   // sH writes done (first iter) / sW reuse safe
        {
            const float4* src = (const float4*)(W2 + (size_t)kk * DIMF);
            float4* dst = (float4*)sW;
            #pragma unroll
            for (int idx = tid; idx < 64 * 128 / 4; idx += NTHREADS)
                dst[idx] = src[idx];
        }
        __syncthreads();

        const float* a0p = sH + (ey + 0) * H_STRIDE + kk;
        const float* a1p = sH + (ey + 1) * H_STRIDE + kk;
        const float* a2p = sH + (ey + 2) * H_STRIDE + kk;
        const float* a3p = sH + (ey + 3) * H_STRIDE + kk;

        #pragma unroll 8
        for (int k = 0; k < 64; k++) {
            unsigned long long pa0 = pack_dup(a0p[k]);
            unsigned long long pa1 = pack_dup(a1p[k]);
            unsigned long long pa2 = pack_dup(a2p[k]);
            unsigned long long pa3 = pack_dup(a3p[k]);
            ulonglong2 w01 = *(const ulonglong2*)&sW[k * 128 + cx];
            ulonglong2 w23 = *(const ulonglong2*)&sW[k * 128 + cx + 4];
            ffma2(acc[0][0], pa0, w01.x); ffma2(acc[0][1], pa0, w01.y);
            ffma2(acc[0][2], pa0, w23.x); ffma2(acc[0][3], pa0, w23.y);
            ffma2(acc[1][0], pa1, w01.x); ffma2(acc[1][1], pa1, w01.y);
            ffma2(acc[1][2], pa1, w23.x); ffma2(acc[1][3], pa1, w23.y);
            ffma2(acc[2][0], pa2, w01.x); ffma2(acc[2][1], pa2, w01.y);
            ffma2(acc[2][2], pa2, w23.x); ffma2(acc[2][3], pa2, w23.y);
            ffma2(acc[3][0], pa3, w01.x); ffma2(acc[3][1], pa3, w01.y);
            ffma2(acc[3][2], pa3, w23.x); ffma2(acc[3][3], pa3, w23.y);
        }
    }

    // ---- epilogue: store out ----
    #pragma unroll
    for (int i = 0; i < 4; i++) {
        int e = eb + ey + i;
        if (e < E) {
            float2 v0 = unpack2(acc[i][0]);
            float2 v1 = unpack2(acc[i][1]);
            float2 v2 = unpack2(acc[i][2]);
            float2 v3 = unpack2(acc[i][3]);
            float4 o0 = make_float4(v0.x, v0.y, v1.x, v1.y);
            float4 o1 = make_float4(v2.x, v2.y, v3.x, v3.y);
            float* orow = out + (size_t)e * DIMF + cx;
            *(float4*)(orow)     = o0;
            *(float4*)(orow + 4) = o1;
        }
    }
}

extern "C" void kernel_launch(void* const* d_in, const int* in_sizes, int n_in,
                              void* d_out, int out_size) {
    const float* node_attr  = (const float*)d_in[0];
    const float* edge_attr  = (const float*)d_in[1];
    const float* W1         = (const float*)d_in[2];
    const float* b1         = (const float*)d_in[3];
    const float* W2         = (const float*)d_in[4];
    const float* b2         = (const float*)d_in[5];
    const int*   cells_node = (const int*)d_in[6];
    // d_in[7] = cells_index: deterministic repeat(arange(C), 3); structure used directly
    const int*   edge_index = (const int*)d_in[8];
    float* out = (float*)d_out;

    const int E = in_sizes[1] / DIMF;
    const int K = in_sizes[6];
    const int C = K / 3;

    // stage 1: cell scatter-sum (8 cells per 256-thread block)
    float* cell_attr = nullptr;
    cudaGetSymbolAddress((void**)&cell_attr, g_cell_attr);
    {
        int blocks = (C + 7) / 8;
        cell_sum_kernel<<<blocks, 256>>>(node_attr, cells_node, cell_attr, C);
    }

    // stage 2: fused edge MLP
    {
        size_t smem_bytes = (size_t)(TILE_E * COLL_STRIDE + 64 * 128 + TILE_E * H_STRIDE) * sizeof(float);
        static bool attr_set = false;
        if (!attr_set) {
            cudaFuncSetAttribute(edge_mlp_kernel,
                                 cudaFuncAttributeMaxDynamicSharedMemorySize,
                                 (int)smem_bytes);
            attr_set = true;
        }
        int blocks = (E + TILE_E - 1) / TILE_E;
        edge_mlp_kernel<<<blocks, NTHREADS, smem_bytes>>>(
            cell_attr, edge_attr, W1, b1, W2, b2, edge_index, out, E);
    }
}

// round 3
// speedup vs baseline: 2.3102x; 2.3102x over previous
#include <cuda_runtime.h>
#include <cuda_bf16.h>
#include <cstdint>

#define DIMF   128
#define TILE_M 128
#define AS_B   272          // smem row stride in bytes (136 bf16)
#define TBUF   34816        // 128 rows * 272 B

// smem byte offsets
#define OFF_B1   0
#define OFF_B2   512
#define OFF_A_HI 1024
#define OFF_A_LO (OFF_A_HI + TBUF)
#define OFF_B_HI (OFF_A_LO + TBUF)
#define OFF_B_LO (OFF_B_HI + TBUF)
#define SMEM_BYTES (OFF_B_LO + TBUF)

// global scratch (no allocs allowed)
__device__ float g_cell_attr[400000 * 128];

// ---------------- helpers ----------------
__device__ __forceinline__ uint32_t smem_u32(const void* p) {
    uint32_t a;
    asm("{ .reg .u64 t; cvta.to.shared.u64 t, %1; cvt.u32.u64 %0, t; }"
        : "=r"(a) : "l"(p));
    return a;
}
__device__ __forceinline__ void sts128(uint32_t addr, uint4 v) {
    asm volatile("st.shared.v4.b32 [%0], {%1,%2,%3,%4};"
                 :: "r"(addr), "r"(v.x), "r"(v.y), "r"(v.z), "r"(v.w));
}
__device__ __forceinline__ void sts32(uint32_t addr, uint32_t v) {
    asm volatile("st.shared.b32 [%0], %1;" :: "r"(addr), "r"(v));
}
__device__ __forceinline__ void ldsm4(uint32_t (&r)[4], uint32_t a) {
    asm volatile("ldmatrix.sync.aligned.m8n8.x4.shared.b16 {%0,%1,%2,%3}, [%4];"
                 : "=r"(r[0]), "=r"(r[1]), "=r"(r[2]), "=r"(r[3]) : "r"(a));
}
__device__ __forceinline__ void ldsm4t(uint32_t (&r)[4], uint32_t a) {
    asm volatile("ldmatrix.sync.aligned.m8n8.x4.trans.shared.b16 {%0,%1,%2,%3}, [%4];"
                 : "=r"(r[0]), "=r"(r[1]), "=r"(r[2]), "=r"(r[3]) : "r"(a));
}
__device__ __forceinline__ void mma_bf16(float (&d)[4], const uint32_t (&a)[4],
                                         const uint32_t* b) {
    asm volatile(
        "mma.sync.aligned.m16n8k16.row.col.f32.bf16.bf16.f32 "
        "{%0,%1,%2,%3}, {%4,%5,%6,%7}, {%8,%9}, {%0,%1,%2,%3};"
        : "+f"(d[0]), "+f"(d[1]), "+f"(d[2]), "+f"(d[3])
        : "r"(a[0]), "r"(a[1]), "r"(a[2]), "r"(a[3]), "r"(b[0]), "r"(b[1]));
}

__device__ __forceinline__ void split2(float a, float b, uint32_t& hi, uint32_t& lo) {
    __nv_bfloat162 hp, lp;
    hp.x = __float2bfloat16(a);
    hp.y = __float2bfloat16(b);
    lp.x = __float2bfloat16(a - __bfloat162float(hp.x));
    lp.y = __float2bfloat16(b - __bfloat162float(hp.y));
    hi = *reinterpret_cast<uint32_t*>(&hp);
    lo = *reinterpret_cast<uint32_t*>(&lp);
}
__device__ __forceinline__ void split8(const float* f, uint4& hi, uint4& lo) {
    split2(f[0], f[1], hi.x, lo.x);
    split2(f[2], f[3], hi.y, lo.y);
    split2(f[4], f[5], hi.z, lo.z);
    split2(f[6], f[7], hi.w, lo.w);
}

// ---------------- stage 1: cell scatter-sum ----------------
__global__ void cell_sum_kernel(const float* __restrict__ node_attr,
                                const int* __restrict__ cells_node,
                                float* __restrict__ cell_attr, int C) {
    int warp = (blockIdx.x * blockDim.x + threadIdx.x) >> 5;
    int lane = threadIdx.x & 31;
    if (warp >= C) return;
    int n0 = cells_node[3 * warp + 0];
    int n1 = cells_node[3 * warp + 1];
    int n2 = cells_node[3 * warp + 2];
    float4 a = ((const float4*)(node_attr + (size_t)n0 * DIMF))[lane];
    float4 b = ((const float4*)(node_attr + (size_t)n1 * DIMF))[lane];
    float4 c = ((const float4*)(node_attr + (size_t)n2 * DIMF))[lane];
    float4 s;
    s.x = a.x + b.x + c.x; s.y = a.y + b.y + c.y;
    s.z = a.z + b.z + c.z; s.w = a.w + b.w + c.w;
    ((float4*)(cell_attr + (size_t)warp * DIMF))[lane] = s;
}

// ---------------- stage 2: mma.sync bf16x3 fused edge MLP ----------------
__global__ __launch_bounds__(256, 1)
void edge_mlp_mma(const float* __restrict__ cell_attr,
                  const float* __restrict__ edge_attr,
                  const float* __restrict__ W1, const float* __restrict__ b1,
                  const float* __restrict__ W2, const float* __restrict__ b2,
                  const int* __restrict__ edge_index,
                  float* __restrict__ out, int E) {
    extern __shared__ char smem[];
    uint32_t sb = smem_u32(smem);
    float* sB1 = (float*)(smem + OFF_B1);
    float* sB2 = (float*)(smem + OFF_B2);
    const uint32_t A_HI = sb + OFF_A_HI;
    const uint32_t A_LO = sb + OFF_A_LO;
    const uint32_t B_HI = sb + OFF_B_HI;
    const uint32_t B_LO = sb + OFF_B_LO;

    const int tid = threadIdx.x;
    const int lane = tid & 31;
    const int wid = tid >> 5;
    const int warp_m = wid >> 2;   // 0..1
    const int warp_n = wid & 3;    // 0..3
    const int eb = blockIdx.x * TILE_M;

    if (tid < 128) { sB1[tid] = b1[tid]; sB2[tid] = b2[tid]; }

    // fill-role decomposition: row = tid/2, half = tid&1 (64 k-cols each)
    const int row = tid >> 1;
    const int hf = tid & 1;
    const int e = eb + row;
    const int ec = (e < E) ? e : (E - 1);
    const int sIdx = edge_index[ec];
    const int rIdx = edge_index[E + ec];
    const float msk = (sIdx != rIdx) ? 1.0f : 0.0f;
    const uint32_t fbase = (uint32_t)(row * AS_B + hf * 128);

    float acc[4][4][4];
#pragma unroll
    for (int i = 0; i < 4; i++)
#pragma unroll
        for (int j = 0; j < 4; j++)
#pragma unroll
            for (int k = 0; k < 4; k++) acc[i][j][k] = 0.0f;

    // compute over one staged 128-K chunk
    auto do_chunk = [&]() {
#pragma unroll
        for (int ks = 0; ks < 8; ks++) {
            const int k0 = ks * 16;
            uint32_t ah[4][4], al[4][4];
            {
                const int arow = warp_m * 64 + (lane & 15);
                const int acol = k0 + ((lane >> 4) << 3);
                const uint32_t aoff = (uint32_t)(arow * AS_B + acol * 2);
#pragma unroll
                for (int mt = 0; mt < 4; mt++) {
                    ldsm4(ah[mt], A_HI + aoff + mt * 16 * AS_B);
                    ldsm4(al[mt], A_LO + aoff + mt * 16 * AS_B);
                }
            }
            uint32_t bh[4][2], bl[4][2];
            {
                const int brow = k0 + (lane & 15);
#pragma unroll
                for (int nb = 0; nb < 2; nb++) {
                    const int bcol = warp_n * 32 + nb * 16 + ((lane >> 4) << 3);
                    const uint32_t boff = (uint32_t)(brow * AS_B + bcol * 2);
                    uint32_t t[4];
                    ldsm4t(t, B_HI + boff);
                    bh[nb * 2][0] = t[0]; bh[nb * 2][1] = t[1];
                    bh[nb * 2 + 1][0] = t[2]; bh[nb * 2 + 1][1] = t[3];
                    ldsm4t(t, B_LO + boff);
                    bl[nb * 2][0] = t[0]; bl[nb * 2][1] = t[1];
                    bl[nb * 2 + 1][0] = t[2]; bl[nb * 2 + 1][1] = t[3];
                }
            }
#pragma unroll
            for (int mt = 0; mt < 4; mt++)
#pragma unroll
                for (int nt = 0; nt < 4; nt++) {
                    mma_bf16(acc[mt][nt], ah[mt], bh[nt]);
                    mma_bf16(acc[mt][nt], al[mt], bh[nt]);
                    mma_bf16(acc[mt][nt], ah[mt], bl[nt]);
                }
        }
    };

    // ---------------- layer 1: 3 K-chunks ----------------
#pragma unroll 1
    for (int c = 0; c < 3; c++) {
        __syncthreads();
        // A fill (collected features, fp32 -> bf16 hi/lo)
        {
            const float* asrc =
                (c == 0) ? cell_attr + (size_t)sIdx * DIMF + hf * 64 :
                (c == 1) ? cell_attr + (size_t)rIdx * DIMF + hf * 64 :
                           edge_attr + (size_t)ec * DIMF + hf * 64;
            const float mm = (c == 1) ? msk : 1.0f;
#pragma unroll
            for (int g = 0; g < 8; g++) {
                float4 f0 = ((const float4*)asrc)[g * 2];
                float4 f1 = ((const float4*)asrc)[g * 2 + 1];
                float fv[8] = {f0.x * mm, f0.y * mm, f0.z * mm, f0.w * mm,
                               f1.x * mm, f1.y * mm, f1.z * mm, f1.w * mm};
                uint4 hi, lo;
                split8(fv, hi, lo);
                sts128(A_HI + fbase + g * 16, hi);
                sts128(A_LO + fbase + g * 16, lo);
            }
        }
        // B fill: W1[c*128 + k][n] is already [k][n] row-major
        {
            const float* bsrc = W1 + (size_t)(c * 128 + row) * DIMF + hf * 64;
#pragma unroll
            for (int g = 0; g < 8; g++) {
                float4 f0 = ((const float4*)bsrc)[g * 2];
                float4 f1 = ((const float4*)bsrc)[g * 2 + 1];
                float fv[8] = {f0.x, f0.y, f0.z, f0.w, f1.x, f1.y, f1.z, f1.w};
                uint4 hi, lo;
                split8(fv, hi, lo);
                sts128(B_HI + fbase + g * 16, hi);
                sts128(B_LO + fbase + g * 16, lo);
            }
        }
        __syncthreads();
        do_chunk();
    }

    __syncthreads();   // all warps done reading layer-1 tiles

    // ---------------- epilogue 1: h = relu(acc + b1) -> A buffers ----------------
#pragma unroll
    for (int mt = 0; mt < 4; mt++)
#pragma unroll
        for (int nt = 0; nt < 4; nt++) {
            const int mrow = warp_m * 64 + mt * 16 + (lane >> 2);
            const int n = warp_n * 32 + nt * 8 + (lane & 3) * 2;
            const float bb0 = sB1[n], bb1 = sB1[n + 1];
            uint32_t hi, lo;
            split2(fmaxf(acc[mt][nt][0] + bb0, 0.0f),
                   fmaxf(acc[mt][nt][1] + bb1, 0.0f), hi, lo);
            sts32(A_HI + mrow * AS_B + n * 2, hi);
            sts32(A_LO + mrow * AS_B + n * 2, lo);
            split2(fmaxf(acc[mt][nt][2] + bb0, 0.0f),
                   fmaxf(acc[mt][nt][3] + bb1, 0.0f), hi, lo);
            sts32(A_HI + (mrow + 8) * AS_B + n * 2, hi);
            sts32(A_LO + (mrow + 8) * AS_B + n * 2, lo);
            acc[mt][nt][0] = 0.0f; acc[mt][nt][1] = 0.0f;
            acc[mt][nt][2] = 0.0f; acc[mt][nt][3] = 0.0f;
        }

    // B fill with W2 [128][128]
    {
        const float* bsrc = W2 + (size_t)row * DIMF + hf * 64;
#pragma unroll
        for (int g = 0; g < 8; g++) {
            float4 f0 = ((const float4*)bsrc)[g * 2];
            float4 f1 = ((const float4*)bsrc)[g * 2 + 1];
            float fv[8] = {f0.x, f0.y, f0.z, f0.w, f1.x, f1.y, f1.z, f1.w};
            uint4 hi, lo;
            split8(fv, hi, lo);
            sts128(B_HI + fbase + g * 16, hi);
            sts128(B_LO + fbase + g * 16, lo);
        }
    }
    __syncthreads();

    // ---------------- layer 2 ----------------
    do_chunk();

    // ---------------- epilogue 2: out = acc + b2 ----------------
#pragma unroll
    for (int mt = 0; mt < 4; mt++)
#pragma unroll
        for (int nt = 0; nt < 4; nt++) {
            const int mrow = warp_m * 64 + mt * 16 + (lane >> 2);
            const int n = warp_n * 32 + nt * 8 + (lane & 3) * 2;
            const float bb0 = sB2[n], bb1 = sB2[n + 1];
            const int e0 = eb + mrow;
            if (e0 < E) {
                float2 o = make_float2(acc[mt][nt][0] + bb0, acc[mt][nt][1] + bb1);
                *(float2*)(out + (size_t)e0 * DIMF + n) = o;
            }
            const int e1 = eb + mrow + 8;
            if (e1 < E) {
                float2 o = make_float2(acc[mt][nt][2] + bb0, acc[mt][nt][3] + bb1);
                *(float2*)(out + (size_t)e1 * DIMF + n) = o;
            }
        }
}

extern "C" void kernel_launch(void* const* d_in, const int* in_sizes, int n_in,
                              void* d_out, int out_size) {
    const float* node_attr  = (const float*)d_in[0];
    const float* edge_attr  = (const float*)d_in[1];
    const float* W1         = (const float*)d_in[2];
    const float* b1         = (const float*)d_in[3];
    const float* W2         = (const float*)d_in[4];
    const float* b2         = (const float*)d_in[5];
    const int*   cells_node = (const int*)d_in[6];
    // d_in[7] = cells_index: deterministic repeat(arange(C),3) — structure used directly
    const int*   edge_index = (const int*)d_in[8];
    float* out = (float*)d_out;

    const int E = in_sizes[1] / DIMF;
    const int C = in_sizes[6] / 3;

    float* cell_attr = nullptr;
    cudaGetSymbolAddress((void**)&cell_attr, g_cell_attr);

    cell_sum_kernel<<<(C + 7) / 8, 256>>>(node_attr, cells_node, cell_attr, C);

    static bool attr_set = false;
    if (!attr_set) {
        cudaFuncSetAttribute(edge_mlp_mma,
                             cudaFuncAttributeMaxDynamicSharedMemorySize, SMEM_BYTES);
        attr_set = true;
    }
    int blocks = (E + TILE_M - 1) / TILE_M;
    edge_mlp_mma<<<blocks, 256, SMEM_BYTES>>>(cell_attr, edge_attr,
                                              W1, b1, W2, b2,
                                              edge_index, out, E);
}

// round 4
// speedup vs baseline: 2.3298x; 1.0085x over previous
#include <cuda_runtime.h>
#include <cuda_bf16.h>
#include <cstdint>

#define DIMF   128
#define TILE_M 128
#define NT     512
#define AS_B   272          // smem row stride in bytes (136 bf16)
#define TBUF   34816        // 128 rows * 272 B

// smem byte offsets
#define OFF_B1   0
#define OFF_B2   512
#define OFF_A_HI 1024
#define OFF_A_LO (OFF_A_HI + TBUF)
#define OFF_B0_HI (OFF_A_LO + TBUF)
#define OFF_B0_LO (OFF_B0_HI + TBUF)
#define OFF_B1_HI (OFF_B0_LO + TBUF)
#define OFF_B1_LO (OFF_B1_HI + TBUF)
#define SMEM_BYTES (OFF_B1_LO + TBUF)   // 209920 B

// global scratch (no allocs allowed)
__device__ float         g_cell_attr[400000 * 128];
__device__ __nv_bfloat16 g_w1_hi[384 * 128];
__device__ __nv_bfloat16 g_w1_lo[384 * 128];
__device__ __nv_bfloat16 g_w2_hi[128 * 128];
__device__ __nv_bfloat16 g_w2_lo[128 * 128];

// ---------------- helpers ----------------
__device__ __forceinline__ uint32_t smem_u32(const void* p) {
    uint32_t a;
    asm("{ .reg .u64 t; cvta.to.shared.u64 t, %1; cvt.u32.u64 %0, t; }"
        : "=r"(a) : "l"(p));
    return a;
}
__device__ __forceinline__ void sts128(uint32_t addr, uint4 v) {
    asm volatile("st.shared.v4.b32 [%0], {%1,%2,%3,%4};"
                 :: "r"(addr), "r"(v.x), "r"(v.y), "r"(v.z), "r"(v.w));
}
__device__ __forceinline__ void sts32(uint32_t addr, uint32_t v) {
    asm volatile("st.shared.b32 [%0], %1;" :: "r"(addr), "r"(v));
}
__device__ __forceinline__ void cpasync16(uint32_t s, const void* g) {
    asm volatile("cp.async.cg.shared.global [%0], [%1], 16;" :: "r"(s), "l"(g));
}
#define CP_COMMIT() asm volatile("cp.async.commit_group;" ::: "memory")
#define CP_WAIT(n)  asm volatile("cp.async.wait_group %0;" :: "n"(n) : "memory")

__device__ __forceinline__ void ldsm4(uint32_t (&r)[4], uint32_t a) {
    asm volatile("ldmatrix.sync.aligned.m8n8.x4.shared.b16 {%0,%1,%2,%3}, [%4];"
                 : "=r"(r[0]), "=r"(r[1]), "=r"(r[2]), "=r"(r[3]) : "r"(a));
}
__device__ __forceinline__ void ldsm4t(uint32_t (&r)[4], uint32_t a) {
    asm volatile("ldmatrix.sync.aligned.m8n8.x4.trans.shared.b16 {%0,%1,%2,%3}, [%4];"
                 : "=r"(r[0]), "=r"(r[1]), "=r"(r[2]), "=r"(r[3]) : "r"(a));
}
__device__ __forceinline__ void mma_bf16(float (&d)[4], const uint32_t (&a)[4],
                                         const uint32_t* b) {
    asm volatile(
        "mma.sync.aligned.m16n8k16.row.col.f32.bf16.bf16.f32 "
        "{%0,%1,%2,%3}, {%4,%5,%6,%7}, {%8,%9}, {%0,%1,%2,%3};"
        : "+f"(d[0]), "+f"(d[1]), "+f"(d[2]), "+f"(d[3])
        : "r"(a[0]), "r"(a[1]), "r"(a[2]), "r"(a[3]), "r"(b[0]), "r"(b[1]));
}

__device__ __forceinline__ void split2(float a, float b, uint32_t& hi, uint32_t& lo) {
    __nv_bfloat162 hp, lp;
    hp.x = __float2bfloat16(a);
    hp.y = __float2bfloat16(b);
    lp.x = __float2bfloat16(a - __bfloat162float(hp.x));
    lp.y = __float2bfloat16(b - __bfloat162float(hp.y));
    hi = *reinterpret_cast<uint32_t*>(&hp);
    lo = *reinterpret_cast<uint32_t*>(&lp);
}
__device__ __forceinline__ void split8(const float* f, uint4& hi, uint4& lo) {
    split2(f[0], f[1], hi.x, lo.x);
    split2(f[2], f[3], hi.y, lo.y);
    split2(f[4], f[5], hi.z, lo.z);
    split2(f[6], f[7], hi.w, lo.w);
}

// ---------------- stage 1: cell scatter-sum ----------------
__global__ void cell_sum_kernel(const float* __restrict__ node_attr,
                                const int* __restrict__ cells_node,
                                float* __restrict__ cell_attr, int C) {
    int warp = (blockIdx.x * blockDim.x + threadIdx.x) >> 5;
    int lane = threadIdx.x & 31;
    if (warp >= C) return;
    int n0 = cells_node[3 * warp + 0];
    int n1 = cells_node[3 * warp + 1];
    int n2 = cells_node[3 * warp + 2];
    float4 a = ((const float4*)(node_attr + (size_t)n0 * DIMF))[lane];
    float4 b = ((const float4*)(node_attr + (size_t)n1 * DIMF))[lane];
    float4 c = ((const float4*)(node_attr + (size_t)n2 * DIMF))[lane];
    float4 s;
    s.x = a.x + b.x + c.x; s.y = a.y + b.y + c.y;
    s.z = a.z + b.z + c.z; s.w = a.w + b.w + c.w;
    ((float4*)(cell_attr + (size_t)warp * DIMF))[lane] = s;
}

// ---------------- stage 1.5: weight bf16 hi/lo split (K-major, no transpose) ----------------
__global__ void prep_w(const float* __restrict__ W1, const float* __restrict__ W2,
                       __nv_bfloat16* __restrict__ w1h, __nv_bfloat16* __restrict__ w1l,
                       __nv_bfloat16* __restrict__ w2h, __nv_bfloat16* __restrict__ w2l) {
    int o = blockIdx.x * blockDim.x + threadIdx.x;
    if (o < 384 * 128) {
        float v = W1[o];
        __nv_bfloat16 h = __float2bfloat16(v);
        w1h[o] = h;
        w1l[o] = __float2bfloat16(v - __bfloat162float(h));
    }
    if (o < 128 * 128) {
        float v = W2[o];
        __nv_bfloat16 h = __float2bfloat16(v);
        w2h[o] = h;
        w2l[o] = __float2bfloat16(v - __bfloat162float(h));
    }
}

// ---------------- stage 2: mma.sync bf16x3 fused edge MLP ----------------
__global__ __launch_bounds__(NT, 1)
void edge_mlp_mma(const float* __restrict__ cell_attr,
                  const float* __restrict__ edge_attr,
                  const __nv_bfloat16* __restrict__ w1h, const __nv_bfloat16* __restrict__ w1l,
                  const __nv_bfloat16* __restrict__ w2h, const __nv_bfloat16* __restrict__ w2l,
                  const float* __restrict__ b1, const float* __restrict__ b2,
                  const int* __restrict__ edge_index,
                  float* __restrict__ out, int E) {
    extern __shared__ char smem[];
    uint32_t sb = smem_u32(smem);
    float* sB1 = (float*)(smem + OFF_B1);
    float* sB2 = (float*)(smem + OFF_B2);
    const uint32_t A_HI = sb + OFF_A_HI;
    const uint32_t A_LO = sb + OFF_A_LO;
    const uint32_t Bbuf_HI[2] = {sb + OFF_B0_HI, sb + OFF_B1_HI};
    const uint32_t Bbuf_LO[2] = {sb + OFF_B0_LO, sb + OFF_B1_LO};

    const int tid = threadIdx.x;
    const int lane = tid & 31;
    const int wid = tid >> 5;
    const int warp_m = wid & 3;    // 0..3 : 32-row tile
    const int warp_n = wid >> 2;   // 0..3 : 32-col tile
    const int eb = blockIdx.x * TILE_M;

    if (tid < 128) { sB1[tid] = b1[tid]; sB2[tid] = b2[tid]; }

    // A-fill decomposition: row = tid/4 (0..127), quarter = tid&3 (32 k-cols)
    const int row = tid >> 2;
    const int q = tid & 3;
    const int e = eb + row;
    const int ec = (e < E) ? e : (E - 1);
    const int sIdx = edge_index[ec];
    const int rIdx = edge_index[E + ec];
    const float msk = (sIdx != rIdx) ? 1.0f : 0.0f;
    const uint32_t fbase = (uint32_t)(row * AS_B + q * 64);

    // B prefetch: 128 rows x 16 x 16B segments, hi + lo
    auto prefetch_B = [&](int buf, const __nv_bfloat16* srcH, const __nv_bfloat16* srcL) {
#pragma unroll
        for (int i = tid; i < 2048; i += NT) {
            int r = i >> 4, s = i & 15;
            uint32_t dst = (uint32_t)(r * AS_B + s * 16);
            cpasync16(Bbuf_HI[buf] + dst, srcH + r * 128 + s * 8);
            cpasync16(Bbuf_LO[buf] + dst, srcL + r * 128 + s * 8);
        }
        CP_COMMIT();
    };

    float acc[2][4][4];
#pragma unroll
    for (int i = 0; i < 2; i++)
#pragma unroll
        for (int j = 0; j < 4; j++)
#pragma unroll
            for (int k = 0; k < 4; k++) acc[i][j][k] = 0.0f;

    auto do_chunk = [&](uint32_t BH, uint32_t BL) {
#pragma unroll
        for (int ks = 0; ks < 8; ks++) {
            const int k0 = ks * 16;
            uint32_t ah[2][4], al[2][4];
            {
                const int arow = warp_m * 32 + (lane & 15);
                const int acol = k0 + ((lane >> 4) << 3);
                const uint32_t aoff = (uint32_t)(arow * AS_B + acol * 2);
#pragma unroll
                for (int mt = 0; mt < 2; mt++) {
                    ldsm4(ah[mt], A_HI + aoff + mt * 16 * AS_B);
                    ldsm4(al[mt], A_LO + aoff + mt * 16 * AS_B);
                }
            }
            uint32_t bh[4][2], bl[4][2];
            {
                const int brow = k0 + (lane & 15);
#pragma unroll
                for (int nb = 0; nb < 2; nb++) {
                    const int bcol = warp_n * 32 + nb * 16 + ((lane >> 4) << 3);
                    const uint32_t boff = (uint32_t)(brow * AS_B + bcol * 2);
                    uint32_t t[4];
                    ldsm4t(t, BH + boff);
                    bh[nb * 2][0] = t[0]; bh[nb * 2][1] = t[1];
                    bh[nb * 2 + 1][0] = t[2]; bh[nb * 2 + 1][1] = t[3];
                    ldsm4t(t, BL + boff);
                    bl[nb * 2][0] = t[0]; bl[nb * 2][1] = t[1];
                    bl[nb * 2 + 1][0] = t[2]; bl[nb * 2 + 1][1] = t[3];
                }
            }
#pragma unroll
            for (int mt = 0; mt < 2; mt++)
#pragma unroll
                for (int nt = 0; nt < 4; nt++) {
                    mma_bf16(acc[mt][nt], ah[mt], bh[nt]);
                    mma_bf16(acc[mt][nt], al[mt], bh[nt]);
                    mma_bf16(acc[mt][nt], ah[mt], bl[nt]);
                }
        }
    };

    // prefetch chunk0 weights
    prefetch_B(0, w1h, w1l);

    // ---------------- layer 1: 3 K-chunks ----------------
#pragma unroll 1
    for (int c = 0; c < 3; c++) {
        __syncthreads();   // A buffer free (prev chunk's MMAs done)
        // A fill (collected features, fp32 -> bf16 hi/lo)
        {
            const float* asrc =
                (c == 0) ? cell_attr + (size_t)sIdx * DIMF + q * 32 :
                (c == 1) ? cell_attr + (size_t)rIdx * DIMF + q * 32 :
                           edge_attr + (size_t)ec * DIMF + q * 32;
            const float mm = (c == 1) ? msk : 1.0f;
#pragma unroll
            for (int g = 0; g < 4; g++) {
                float4 f0 = ((const float4*)asrc)[g * 2];
                float4 f1 = ((const float4*)asrc)[g * 2 + 1];
                float fv[8] = {f0.x * mm, f0.y * mm, f0.z * mm, f0.w * mm,
                               f1.x * mm, f1.y * mm, f1.z * mm, f1.w * mm};
                uint4 hi, lo;
                split8(fv, hi, lo);
                sts128(A_HI + fbase + g * 16, hi);
                sts128(A_LO + fbase + g * 16, lo);
            }
        }
        // prefetch next weights into the other buffer
        if (c < 2) prefetch_B((c + 1) & 1, w1h + (c + 1) * 16384, w1l + (c + 1) * 16384);
        else       prefetch_B(1, w2h, w2l);
        CP_WAIT(1);        // chunk c's weights are resident
        __syncthreads();
        do_chunk(Bbuf_HI[c & 1], Bbuf_LO[c & 1]);
    }

    __syncthreads();   // all warps done reading layer-1 A tiles

    // ---------------- epilogue 1: h = relu(acc + b1) -> A buffers ----------------
#pragma unroll
    for (int mt = 0; mt < 2; mt++)
#pragma unroll
        for (int nt = 0; nt < 4; nt++) {
            const int mrow = warp_m * 32 + mt * 16 + (lane >> 2);
            const int n = warp_n * 32 + nt * 8 + (lane & 3) * 2;
            const float bb0 = sB1[n], bb1 = sB1[n + 1];
            uint32_t hi, lo;
            split2(fmaxf(acc[mt][nt][0] + bb0, 0.0f),
                   fmaxf(acc[mt][nt][1] + bb1, 0.0f), hi, lo);
            sts32(A_HI + mrow * AS_B + n * 2, hi);
            sts32(A_LO + mrow * AS_B + n * 2, lo);
            split2(fmaxf(acc[mt][nt][2] + bb0, 0.0f),
                   fmaxf(acc[mt][nt][3] + bb1, 0.0f), hi, lo);
            sts32(A_HI + (mrow + 8) * AS_B + n * 2, hi);
            sts32(A_LO + (mrow + 8) * AS_B + n * 2, lo);
            acc[mt][nt][0] = 0.0f; acc[mt][nt][1] = 0.0f;
            acc[mt][nt][2] = 0.0f; acc[mt][nt][3] = 0.0f;
        }

    CP_WAIT(0);        // W2 resident (buffer 1)
    __syncthreads();

    // ---------------- layer 2 ----------------
    do_chunk(Bbuf_HI[1], Bbuf_LO[1]);

    // ---------------- epilogue 2: out = acc + b2 ----------------
#pragma unroll
    for (int mt = 0; mt < 2; mt++)
#pragma unroll
        for (int nt = 0; nt < 4; nt++) {
            const int mrow = warp_m * 32 + mt * 16 + (lane >> 2);
            const int n = warp_n * 32 + nt * 8 + (lane & 3) * 2;
            const float bb0 = sB2[n], bb1 = sB2[n + 1];
            const int e0 = eb + mrow;
            if (e0 < E) {
                float2 o = make_float2(acc[mt][nt][0] + bb0, acc[mt][nt][1] + bb1);
                *(float2*)(out + (size_t)e0 * DIMF + n) = o;
            }
            const int e1 = eb + mrow + 8;
            if (e1 < E) {
                float2 o = make_float2(acc[mt][nt][2] + bb0, acc[mt][nt][3] + bb1);
                *(float2*)(out + (size_t)e1 * DIMF + n) = o;
            }
        }
}

extern "C" void kernel_launch(void* const* d_in, const int* in_sizes, int n_in,
                              void* d_out, int out_size) {
    const float* node_attr  = (const float*)d_in[0];
    const float* edge_attr  = (const float*)d_in[1];
    const float* W1         = (const float*)d_in[2];
    const float* b1         = (const float*)d_in[3];
    const float* W2         = (const float*)d_in[4];
    const float* b2         = (const float*)d_in[5];
    const int*   cells_node = (const int*)d_in[6];
    // d_in[7] = cells_index: deterministic repeat(arange(C),3) — structure used directly
    const int*   edge_index = (const int*)d_in[8];
    float* out = (float*)d_out;

    const int E = in_sizes[1] / DIMF;
    const int C = in_sizes[6] / 3;

    float* cell_attr = nullptr;
    __nv_bfloat16 *w1h, *w1l, *w2h, *w2l;
    cudaGetSymbolAddress((void**)&cell_attr, g_cell_attr);
    cudaGetSymbolAddress((void**)&w1h, g_w1_hi);
    cudaGetSymbolAddress((void**)&w1l, g_w1_lo);
    cudaGetSymbolAddress((void**)&w2h, g_w2_hi);
    cudaGetSymbolAddress((void**)&w2l, g_w2_lo);

    cell_sum_kernel<<<(C + 7) / 8, 256>>>(node_attr, cells_node, cell_attr, C);
    prep_w<<<(384 * 128 + 255) / 256, 256>>>(W1, W2, w1h, w1l, w2h, w2l);

    static bool attr_set = false;
    if (!attr_set) {
        cudaFuncSetAttribute(edge_mlp_mma,
                             cudaFuncAttributeMaxDynamicSharedMemorySize, SMEM_BYTES);
        attr_set = true;
    }
    int blocks = (E + TILE_M - 1) / TILE_M;
    edge_mlp_mma<<<blocks, NT, SMEM_BYTES>>>(cell_attr, edge_attr,
                                             w1h, w1l, w2h, w2l,
                                             b1, b2, edge_index, out, E);
}

// round 5
// speedup vs baseline: 2.8122x; 1.2071x over previous
#include <cuda_runtime.h>
#include <cuda_bf16.h>
#include <cstdint>

#define DIMF   128
#define TILE_M 64
#define NT     256
#define AS_B   272          // smem row stride in bytes (136 bf16)
#define ABUF   17408        // 64 rows * 272 B
#define BBUF   34816        // 128 rows * 272 B

// smem byte offsets
#define OFF_B1   0
#define OFF_B2   512
#define OFF_A_HI 1024
#define OFF_A_LO (OFF_A_HI + ABUF)
#define OFF_B_HI (OFF_A_LO + ABUF)
#define OFF_B_LO (OFF_B_HI + BBUF)
#define SMEM_BYTES (OFF_B_LO + BBUF)   // 105,472 B -> 2 CTAs/SM

// global scratch (no allocs allowed)
__device__ float         g_cell_attr[400000 * 128];
__device__ __nv_bfloat16 g_w1_hi[384 * 128];
__device__ __nv_bfloat16 g_w1_lo[384 * 128];
__device__ __nv_bfloat16 g_w2_hi[128 * 128];
__device__ __nv_bfloat16 g_w2_lo[128 * 128];

// ---------------- helpers ----------------
__device__ __forceinline__ uint32_t smem_u32(const void* p) {
    uint32_t a;
    asm("{ .reg .u64 t; cvta.to.shared.u64 t, %1; cvt.u32.u64 %0, t; }"
        : "=r"(a) : "l"(p));
    return a;
}
__device__ __forceinline__ void sts128(uint32_t addr, uint4 v) {
    asm volatile("st.shared.v4.b32 [%0], {%1,%2,%3,%4};"
                 :: "r"(addr), "r"(v.x), "r"(v.y), "r"(v.z), "r"(v.w));
}
__device__ __forceinline__ void sts32(uint32_t addr, uint32_t v) {
    asm volatile("st.shared.b32 [%0], %1;" :: "r"(addr), "r"(v));
}
__device__ __forceinline__ void cpasync16(uint32_t s, const void* g) {
    asm volatile("cp.async.cg.shared.global [%0], [%1], 16;" :: "r"(s), "l"(g));
}
#define CP_COMMIT() asm volatile("cp.async.commit_group;" ::: "memory")
#define CP_WAIT(n)  asm volatile("cp.async.wait_group %0;" :: "n"(n) : "memory")

__device__ __forceinline__ void ldsm4(uint32_t (&r)[4], uint32_t a) {
    asm volatile("ldmatrix.sync.aligned.m8n8.x4.shared.b16 {%0,%1,%2,%3}, [%4];"
                 : "=r"(r[0]), "=r"(r[1]), "=r"(r[2]), "=r"(r[3]) : "r"(a));
}
__device__ __forceinline__ void ldsm4t(uint32_t (&r)[4], uint32_t a) {
    asm volatile("ldmatrix.sync.aligned.m8n8.x4.trans.shared.b16 {%0,%1,%2,%3}, [%4];"
                 : "=r"(r[0]), "=r"(r[1]), "=r"(r[2]), "=r"(r[3]) : "r"(a));
}
__device__ __forceinline__ void mma_bf16(float (&d)[4], const uint32_t (&a)[4],
                                         const uint32_t* b) {
    asm volatile(
        "mma.sync.aligned.m16n8k16.row.col.f32.bf16.bf16.f32 "
        "{%0,%1,%2,%3}, {%4,%5,%6,%7}, {%8,%9}, {%0,%1,%2,%3};"
        : "+f"(d[0]), "+f"(d[1]), "+f"(d[2]), "+f"(d[3])
        : "r"(a[0]), "r"(a[1]), "r"(a[2]), "r"(a[3]), "r"(b[0]), "r"(b[1]));
}

__device__ __forceinline__ void split2(float a, float b, uint32_t& hi, uint32_t& lo) {
    __nv_bfloat162 hp, lp;
    hp.x = __float2bfloat16(a);
    hp.y = __float2bfloat16(b);
    lp.x = __float2bfloat16(a - __bfloat162float(hp.x));
    lp.y = __float2bfloat16(b - __bfloat162float(hp.y));
    hi = *reinterpret_cast<uint32_t*>(&hp);
    lo = *reinterpret_cast<uint32_t*>(&lp);
}
__device__ __forceinline__ void split8(const float* f, uint4& hi, uint4& lo) {
    split2(f[0], f[1], hi.x, lo.x);
    split2(f[2], f[3], hi.y, lo.y);
    split2(f[4], f[5], hi.z, lo.z);
    split2(f[6], f[7], hi.w, lo.w);
}

// ---------------- stage 1: cell scatter-sum ----------------
__global__ void cell_sum_kernel(const float* __restrict__ node_attr,
                                const int* __restrict__ cells_node,
                                float* __restrict__ cell_attr, int C) {
    int warp = (blockIdx.x * blockDim.x + threadIdx.x) >> 5;
    int lane = threadIdx.x & 31;
    if (warp >= C) return;
    int n0 = cells_node[3 * warp + 0];
    int n1 = cells_node[3 * warp + 1];
    int n2 = cells_node[3 * warp + 2];
    float4 a = ((const float4*)(node_attr + (size_t)n0 * DIMF))[lane];
    float4 b = ((const float4*)(node_attr + (size_t)n1 * DIMF))[lane];
    float4 c = ((const float4*)(node_attr + (size_t)n2 * DIMF))[lane];
    float4 s;
    s.x = a.x + b.x + c.x; s.y = a.y + b.y + c.y;
    s.z = a.z + b.z + c.z; s.w = a.w + b.w + c.w;
    ((float4*)(cell_attr + (size_t)warp * DIMF))[lane] = s;
}

// ---------------- stage 1.5: weight bf16 hi/lo split ----------------
__global__ void prep_w(const float* __restrict__ W1, const float* __restrict__ W2,
                       __nv_bfloat16* __restrict__ w1h, __nv_bfloat16* __restrict__ w1l,
                       __nv_bfloat16* __restrict__ w2h, __nv_bfloat16* __restrict__ w2l) {
    int o = blockIdx.x * blockDim.x + threadIdx.x;
    if (o < 384 * 128) {
        float v = W1[o];
        __nv_bfloat16 h = __float2bfloat16(v);
        w1h[o] = h;
        w1l[o] = __float2bfloat16(v - __bfloat162float(h));
    }
    if (o < 128 * 128) {
        float v = W2[o];
        __nv_bfloat16 h = __float2bfloat16(v);
        w2h[o] = h;
        w2l[o] = __float2bfloat16(v - __bfloat162float(h));
    }
}

// ---------------- stage 2: mma.sync bf16x3 fused edge MLP ----------------
// TILE_M=64 edges/CTA, 105.5 KB smem -> 2 CTAs/SM for cross-CTA latency hiding.
__global__ __launch_bounds__(NT, 2)
void edge_mlp_mma(const float* __restrict__ cell_attr,
                  const float* __restrict__ edge_attr,
                  const __nv_bfloat16* __restrict__ w1h, const __nv_bfloat16* __restrict__ w1l,
                  const __nv_bfloat16* __restrict__ w2h, const __nv_bfloat16* __restrict__ w2l,
                  const float* __restrict__ b1, const float* __restrict__ b2,
                  const int* __restrict__ edge_index,
                  float* __restrict__ out, int E) {
    extern __shared__ char smem[];
    uint32_t sb = smem_u32(smem);
    float* sB1 = (float*)(smem + OFF_B1);
    float* sB2 = (float*)(smem + OFF_B2);
    const uint32_t A_HI = sb + OFF_A_HI;
    const uint32_t A_LO = sb + OFF_A_LO;
    const uint32_t B_HI = sb + OFF_B_HI;
    const uint32_t B_LO = sb + OFF_B_LO;

    const int tid = threadIdx.x;
    const int lane = tid & 31;
    const int wid = tid >> 5;
    const int warp_m = wid >> 2;   // 0..1 : 32-row tile
    const int warp_n = wid & 3;    // 0..3 : 32-col tile
    const int eb = blockIdx.x * TILE_M;

    if (tid < 128) { sB1[tid] = b1[tid]; sB2[tid] = b2[tid]; }

    // A-fill decomposition: row = tid/4 (0..63), quarter = tid&3 (32 k-cols)
    const int row = tid >> 2;
    const int q = tid & 3;
    const int e = eb + row;
    const int ec = (e < E) ? e : (E - 1);
    const int sIdx = edge_index[ec];
    const int rIdx = edge_index[E + ec];
    const float msk = (sIdx != rIdx) ? 1.0f : 0.0f;
    const uint32_t fbase = (uint32_t)(row * AS_B + q * 64);

    // B fill: 128 rows x 16 x 16B segments, hi + lo (cp.async)
    auto fill_B = [&](const __nv_bfloat16* srcH, const __nv_bfloat16* srcL) {
#pragma unroll
        for (int i = tid; i < 2048; i += NT) {
            int r = i >> 4, s = i & 15;
            uint32_t dst = (uint32_t)(r * AS_B + s * 16);
            cpasync16(B_HI + dst, srcH + r * 128 + s * 8);
            cpasync16(B_LO + dst, srcL + r * 128 + s * 8);
        }
        CP_COMMIT();
    };

    float acc[2][4][4];
#pragma unroll
    for (int i = 0; i < 2; i++)
#pragma unroll
        for (int j = 0; j < 4; j++)
#pragma unroll
            for (int k = 0; k < 4; k++) acc[i][j][k] = 0.0f;

    auto do_chunk = [&]() {
#pragma unroll
        for (int ks = 0; ks < 8; ks++) {
            const int k0 = ks * 16;
            uint32_t ah[2][4], al[2][4];
            {
                const int arow = warp_m * 32 + (lane & 15);
                const int acol = k0 + ((lane >> 4) << 3);
                const uint32_t aoff = (uint32_t)(arow * AS_B + acol * 2);
#pragma unroll
                for (int mt = 0; mt < 2; mt++) {
                    ldsm4(ah[mt], A_HI + aoff + mt * 16 * AS_B);
                    ldsm4(al[mt], A_LO + aoff + mt * 16 * AS_B);
                }
            }
            uint32_t bh[4][2], bl[4][2];
            {
                const int brow = k0 + (lane & 15);
#pragma unroll
                for (int nb = 0; nb < 2; nb++) {
                    const int bcol = warp_n * 32 + nb * 16 + ((lane >> 4) << 3);
                    const uint32_t boff = (uint32_t)(brow * AS_B + bcol * 2);
                    uint32_t t[4];
                    ldsm4t(t, B_HI + boff);
                    bh[nb * 2][0] = t[0]; bh[nb * 2][1] = t[1];
                    bh[nb * 2 + 1][0] = t[2]; bh[nb * 2 + 1][1] = t[3];
                    ldsm4t(t, B_LO + boff);
                    bl[nb * 2][0] = t[0]; bl[nb * 2][1] = t[1];
                    bl[nb * 2 + 1][0] = t[2]; bl[nb * 2 + 1][1] = t[3];
                }
            }
#pragma unroll
            for (int mt = 0; mt < 2; mt++)
#pragma unroll
                for (int nt = 0; nt < 4; nt++) {
                    mma_bf16(acc[mt][nt], ah[mt], bh[nt]);
                    mma_bf16(acc[mt][nt], al[mt], bh[nt]);
                    mma_bf16(acc[mt][nt], ah[mt], bl[nt]);
                }
        }
    };

    // ---------------- layer 1: 3 K-chunks ----------------
#pragma unroll 1
    for (int c = 0; c < 3; c++) {
        __syncthreads();   // A and B buffers free (prev chunk MMAs done)
        // B fill rides under the A gather
        fill_B(w1h + c * 16384, w1l + c * 16384);
        // A fill (collected features, fp32 -> bf16 hi/lo)
        {
            const float* asrc =
                (c == 0) ? cell_attr + (size_t)sIdx * DIMF + q * 32 :
                (c == 1) ? cell_attr + (size_t)rIdx * DIMF + q * 32 :
                           edge_attr + (size_t)ec * DIMF + q * 32;
            const float mm = (c == 1) ? msk : 1.0f;
#pragma unroll
            for (int g = 0; g < 4; g++) {
                float4 f0 = ((const float4*)asrc)[g * 2];
                float4 f1 = ((const float4*)asrc)[g * 2 + 1];
                float fv[8] = {f0.x * mm, f0.y * mm, f0.z * mm, f0.w * mm,
                               f1.x * mm, f1.y * mm, f1.z * mm, f1.w * mm};
                uint4 hi, lo;
                split8(fv, hi, lo);
                sts128(A_HI + fbase + g * 16, hi);
                sts128(A_LO + fbase + g * 16, lo);
            }
        }
        CP_WAIT(0);
        __syncthreads();
        do_chunk();
    }

    __syncthreads();   // all warps done reading layer-1 A/B tiles

    // W2 fill rides under the epilogue
    fill_B(w2h, w2l);

    // ---------------- epilogue 1: h = relu(acc + b1) -> A buffers ----------------
#pragma unroll
    for (int mt = 0; mt < 2; mt++)
#pragma unroll
        for (int nt = 0; nt < 4; nt++) {
            const int mrow = warp_m * 32 + mt * 16 + (lane >> 2);
            const int n = warp_n * 32 + nt * 8 + (lane & 3) * 2;
            const float bb0 = sB1[n], bb1 = sB1[n + 1];
            uint32_t hi, lo;
            split2(fmaxf(acc[mt][nt][0] + bb0, 0.0f),
                   fmaxf(acc[mt][nt][1] + bb1, 0.0f), hi, lo);
            sts32(A_HI + mrow * AS_B + n * 2, hi);
            sts32(A_LO + mrow * AS_B + n * 2, lo);
            split2(fmaxf(acc[mt][nt][2] + bb0, 0.0f),
                   fmaxf(acc[mt][nt][3] + bb1, 0.0f), hi, lo);
            sts32(A_HI + (mrow + 8) * AS_B + n * 2, hi);
            sts32(A_LO + (mrow + 8) * AS_B + n * 2, lo);
            acc[mt][nt][0] = 0.0f; acc[mt][nt][1] = 0.0f;
            acc[mt][nt][2] = 0.0f; acc[mt][nt][3] = 0.0f;
        }

    CP_WAIT(0);
    __syncthreads();

    // ---------------- layer 2 ----------------
    do_chunk();

    // ---------------- epilogue 2: out = acc + b2 ----------------
#pragma unroll
    for (int mt = 0; mt < 2; mt++)
#pragma unroll
        for (int nt = 0; nt < 4; nt++) {
            const int mrow = warp_m * 32 + mt * 16 + (lane >> 2);
            const int n = warp_n * 32 + nt * 8 + (lane & 3) * 2;
            const float bb0 = sB2[n], bb1 = sB2[n + 1];
            const int e0 = eb + mrow;
            if (e0 < E) {
                float2 o = make_float2(acc[mt][nt][0] + bb0, acc[mt][nt][1] + bb1);
                *(float2*)(out + (size_t)e0 * DIMF + n) = o;
            }
            const int e1 = eb + mrow + 8;
            if (e1 < E) {
                float2 o = make_float2(acc[mt][nt][2] + bb0, acc[mt][nt][3] + bb1);
                *(float2*)(out + (size_t)e1 * DIMF + n) = o;
            }
        }
}

extern "C" void kernel_launch(void* const* d_in, const int* in_sizes, int n_in,
                              void* d_out, int out_size) {
    const float* node_attr  = (const float*)d_in[0];
    const float* edge_attr  = (const float*)d_in[1];
    const float* W1         = (const float*)d_in[2];
    const float* b1         = (const float*)d_in[3];
    const float* W2         = (const float*)d_in[4];
    const float* b2         = (const float*)d_in[5];
    const int*   cells_node = (const int*)d_in[6];
    // d_in[7] = cells_index: deterministic repeat(arange(C),3) — structure used directly
    const int*   edge_index = (const int*)d_in[8];
    float* out = (float*)d_out;

    const int E = in_sizes[1] / DIMF;
    const int C = in_sizes[6] / 3;

    float* cell_attr = nullptr;
    __nv_bfloat16 *w1h, *w1l, *w2h, *w2l;
    cudaGetSymbolAddress((void**)&cell_attr, g_cell_attr);
    cudaGetSymbolAddress((void**)&w1h, g_w1_hi);
    cudaGetSymbolAddress((void**)&w1l, g_w1_lo);
    cudaGetSymbolAddress((void**)&w2h, g_w2_hi);
    cudaGetSymbolAddress((void**)&w2l, g_w2_lo);

    cell_sum_kernel<<<(C + 7) / 8, 256>>>(node_attr, cells_node, cell_attr, C);
    prep_w<<<(384 * 128 + 255) / 256, 256>>>(W1, W2, w1h, w1l, w2h, w2l);

    static bool attr_set = false;
    if (!attr_set) {
        cudaFuncSetAttribute(edge_mlp_mma,
                             cudaFuncAttributeMaxDynamicSharedMemorySize, SMEM_BYTES);
        attr_set = true;
    }
    int blocks = (E + TILE_M - 1) / TILE_M;
    edge_mlp_mma<<<blocks, NT, SMEM_BYTES>>>(cell_attr, edge_attr,
                                             w1h, w1l, w2h, w2l,
                                             b1, b2, edge_index, out, E);
}